// round 1
// baseline (speedup 1.0000x reference)
#include <cuda_runtime.h>

// LSTM: B=1024, T=2048, H=32, I=1 (fixed by the dataset instance).
// One warp per batch element. Lane j owns hidden unit j.
// Gates packed (i,f) and (g,o) in f32x2; h broadcast via duplicated smem pairs.

#define B_ 1024
#define T_ 2048
#define H_ 32

static __device__ __forceinline__ unsigned long long pk2(float lo, float hi) {
    unsigned long long r;
    asm("mov.b64 %0, {%1, %2};" : "=l"(r) : "f"(lo), "f"(hi));
    return r;
}
static __device__ __forceinline__ void upk2(unsigned long long v, float& lo, float& hi) {
    asm("mov.b64 {%0, %1}, %2;" : "=f"(lo), "=f"(hi) : "l"(v));
}
static __device__ __forceinline__ unsigned long long fma2(unsigned long long a,
                                                          unsigned long long b,
                                                          unsigned long long c) {
    unsigned long long d;
    asm("fma.rn.f32x2 %0, %1, %2, %3;" : "=l"(d) : "l"(a), "l"(b), "l"(c));
    return d;
}
static __device__ __forceinline__ unsigned long long add2(unsigned long long a,
                                                          unsigned long long b) {
    unsigned long long d;
    asm("add.rn.f32x2 %0, %1, %2;" : "=l"(d) : "l"(a), "l"(b));
    return d;
}
static __device__ __forceinline__ float ex2f(float x) {
    float r; asm("ex2.approx.f32 %0, %1;" : "=f"(r) : "f"(x)); return r;
}
static __device__ __forceinline__ float rcpf(float x) {
    float r; asm("rcp.approx.f32 %0, %1;" : "=f"(r) : "f"(x)); return r;
}

__global__ void __launch_bounds__(32)
lstm_kernel(const float* __restrict__ x,
            const float* __restrict__ W_ih,
            const float* __restrict__ W_hh,
            const float* __restrict__ b_ih,
            const float* __restrict__ b_hh,
            const float* __restrict__ W_out,
            const float* __restrict__ b_out,
            float* __restrict__ out) {
    const int j = threadIdx.x;   // hidden unit
    const int b = blockIdx.x;    // batch element

    __shared__ unsigned long long hb[2][H_];  // duplicated (h,h) pairs, double-buffered
    __shared__ float pbuf[32][33];            // per-step output partials (padded)

    const float L = 1.4426950408889634f;      // log2(e)
    const float sI = -L, sF = -L, sG = -2.0f * L, sO = -L;

    // Load + pre-scale recurrent weights into registers as packed pairs.
    // wif[k] = (sI*Whh[i_row][k], sF*Whh[f_row][k]); wgo[k] = (sG*Whh[g_row][k], sO*Whh[o_row][k])
    unsigned long long wif[H_], wgo[H_];
#pragma unroll
    for (int k = 0; k < H_; k++) {
        wif[k] = pk2(sI * W_hh[(0 * H_ + j) * H_ + k],
                     sF * W_hh[(1 * H_ + j) * H_ + k]);
        wgo[k] = pk2(sG * W_hh[(2 * H_ + j) * H_ + k],
                     sO * W_hh[(3 * H_ + j) * H_ + k]);
    }
    const unsigned long long wih_if = pk2(sI * W_ih[0 * H_ + j], sF * W_ih[1 * H_ + j]);
    const unsigned long long wih_go = pk2(sG * W_ih[2 * H_ + j], sO * W_ih[3 * H_ + j]);
    const unsigned long long bs_if  = pk2(sI * (b_ih[0 * H_ + j] + b_hh[0 * H_ + j]),
                                          sF * (b_ih[1 * H_ + j] + b_hh[1 * H_ + j]));
    const unsigned long long bs_go  = pk2(sG * (b_ih[2 * H_ + j] + b_hh[2 * H_ + j]),
                                          sO * (b_ih[3 * H_ + j] + b_hh[3 * H_ + j]));
    const float wout = W_out[j];
    const float bout = b_out[0];
    const unsigned long long z2 = 0ull;  // packed (0.0f, 0.0f)

    float c = 0.0f;
    hb[0][j] = 0ull;   // h_{-1} = 0
    __syncwarp();

    const float* xb = x + (size_t)b * T_;
    float* ob = out + (size_t)b * T_;
    float xc = xb[0];

    for (int t0 = 0; t0 < T_; t0 += 32) {
#pragma unroll 2
        for (int tt = 0; tt < 32; ++tt) {
            const int t = t0 + tt;
            // prefetch next x (broadcast load, L1-resident)
            const int tn = (t + 1 < T_) ? (t + 1) : (T_ - 1);
            const float xn = xb[tn];

            const unsigned long long xd = pk2(xc, xc);
            unsigned long long a0 = fma2(xd, wih_if, bs_if);  // (i,f) preact (pre-scaled)
            unsigned long long a1 = z2;
            unsigned long long g0 = fma2(xd, wih_go, bs_go);  // (g,o) preact (pre-scaled)
            unsigned long long g1 = z2;

            const unsigned long long* hp = hb[t & 1];
#pragma unroll
            for (int k = 0; k < H_; k += 2) {
                const unsigned long long h0 = hp[k];
                const unsigned long long h1 = hp[k + 1];
                a0 = fma2(h0, wif[k],     a0);
                g0 = fma2(h0, wgo[k],     g0);
                a1 = fma2(h1, wif[k + 1], a1);
                g1 = fma2(h1, wgo[k + 1], g1);
            }
            const unsigned long long aif = add2(a0, a1);
            const unsigned long long ago = add2(g0, g1);

            float ai, af, ag, ao;
            upk2(aif, ai, af);
            upk2(ago, ag, ao);

            // sigmoid(a) = 1/(1+exp(-a)) = rcp(1 + ex2(-L*a)); a' already = -L*a
            const float i_ = rcpf(1.0f + ex2f(ai));
            const float f_ = rcpf(1.0f + ex2f(af));
            // tanh(a) = 2/(1+exp(-2a)) - 1; a' already = -2L*a
            const float g_ = fmaf(rcpf(1.0f + ex2f(ag)), 2.0f, -1.0f);
            const float o_ = rcpf(1.0f + ex2f(ao));

            c = fmaf(f_, c, i_ * g_);
            const float tc = fmaf(rcpf(1.0f + ex2f(c * sG)), 2.0f, -1.0f);
            const float h = o_ * tc;

            hb[(t + 1) & 1][j] = pk2(h, h);
            pbuf[tt][j] = h * wout;
            __syncwarp();
            xc = xn;
        }
        // transposed reduction: lane j sums the 32 partials of timestep t0+j
        float s0 = 0.0f, s1 = 0.0f;
#pragma unroll
        for (int k = 0; k < 32; k += 2) {
            s0 += pbuf[j][k];
            s1 += pbuf[j][k + 1];
        }
        ob[t0 + j] = s0 + s1 + bout;
        __syncwarp();  // protect pbuf before next block overwrites row 0
    }
}

extern "C" void kernel_launch(void* const* d_in, const int* in_sizes, int n_in,
                              void* d_out, int out_size) {
    const float* x     = (const float*)d_in[0];
    const float* W_ih  = (const float*)d_in[1];
    const float* W_hh  = (const float*)d_in[2];
    const float* b_ih  = (const float*)d_in[3];
    const float* b_hh  = (const float*)d_in[4];
    const float* W_out = (const float*)d_in[5];
    const float* b_out = (const float*)d_in[6];
    float* out = (float*)d_out;

    lstm_kernel<<<B_, 32>>>(x, W_ih, W_hh, b_ih, b_hh, W_out, b_out, out);
}